// round 7
// baseline (speedup 1.0000x reference)
#include <cuda_runtime.h>
#include <math.h>

#define B_   2
#define T_   2048
#define D_   1024
#define H_   16
#define HKV_ 4
#define HD_  64
#define KV_  256
#define BT_  (B_ * T_)
#define EPS_ 1.1920928955078125e-07f
#define KT   32   // gemm K-tile
#define AST  36   // gemm smem row stride (words)
#define FST  68   // flash K/P smem stride (words)
#define VST  72   // flash V smem stride (words)

// ---------------- scratch (static device globals; no runtime alloc) --------
__device__ float g_qraw[BT_ * D_];          // [BT, 1024] raw q projection
__device__ float g_kraw[BT_ * KV_];         // [BT, 256]
__device__ float g_vraw[BT_ * KV_];         // [BT, 256] (flash reads V here)
__device__ float g_q[B_ * H_ * T_ * HD_];   // [B,H,T,hd] normed+rope+gain+scale
__device__ float g_k[B_ * HKV_ * T_ * HD_]; // [B,Hkv,T,hd] normed+rope
__device__ float g_y[BT_ * D_];             // attention output [BT, 1024]
__device__ float g_invf[32];                // rope inv_freq table

// ---------------- inv_freq table (double pow once) -------------------------
__global__ void k_freq() {
    int i = threadIdx.x;
    if (i < 32) g_invf[i] = (float)pow(10000.0, -(double)i / 32.0);
}

// ---------------- tf32 helpers ---------------------------------------------
__device__ __forceinline__ unsigned f2tf(float f) {
    unsigned r;
    asm("cvt.rna.tf32.f32 %0, %1;" : "=r"(r) : "f"(f));
    return r;
}

__device__ __forceinline__ void mma_tf32v(float c[4], unsigned a0, unsigned a1,
                                          unsigned a2, unsigned a3,
                                          unsigned b0, unsigned b1) {
    asm volatile(
        "mma.sync.aligned.m16n8k8.row.col.f32.tf32.tf32.f32 "
        "{%0,%1,%2,%3}, {%4,%5,%6,%7}, {%8,%9}, {%0,%1,%2,%3};"
        : "+f"(c[0]), "+f"(c[1]), "+f"(c[2]), "+f"(c[3])
        : "r"(a0), "r"(a1), "r"(a2), "r"(a3), "r"(b0), "r"(b1));
}

// ---------------- tf32 GEMM: C[m,n] = sum_k A[m,k]*W[n,k] ------------------
// Block 128x128xKT, 128 threads = 4 warps (2M x 2N), warp tile 64x64.
// tf32 conversion at STS time (same values as R4 -> identical numerics).
__device__ __forceinline__ void gemm_tf32(const float* __restrict__ A,
                                          const float* __restrict__ W,
                                          float* __restrict__ C,
                                          int K, int N, int bm, int bn) {
    __shared__ unsigned As[128 * AST];
    __shared__ unsigned Ws[128 * AST];
    const int tid  = threadIdx.x;
    const int lane = tid & 31;
    const int w    = tid >> 5;      // 0..3
    const int g    = lane >> 2;     // 0..7
    const int tig  = lane & 3;      // 0..3
    const int wm   = (w & 1) * 64;  // warp M offset
    const int wn   = (w >> 1) * 64; // warp N offset

    const float* Ap = A + (size_t)(bm + tid) * K;  // one full row per thread
    const float* Wp = W + (size_t)(bn + tid) * K;

    float acc[4][8][4];
#pragma unroll
    for (int mi = 0; mi < 4; mi++)
#pragma unroll
        for (int ni = 0; ni < 8; ni++)
#pragma unroll
            for (int r = 0; r < 4; r++) acc[mi][ni][r] = 0.0f;

    for (int k0 = 0; k0 < K; k0 += KT) {
        __syncthreads();  // prior iteration's mma reads complete
#pragma unroll
        for (int i = 0; i < 8; i++) {
            float4 v = *(const float4*)(Ap + k0 + 4 * i);
            unsigned* d = &As[tid * AST + 4 * i];
            d[0] = f2tf(v.x); d[1] = f2tf(v.y);
            d[2] = f2tf(v.z); d[3] = f2tf(v.w);
        }
#pragma unroll
        for (int i = 0; i < 8; i++) {
            float4 v = *(const float4*)(Wp + k0 + 4 * i);
            unsigned* d = &Ws[tid * AST + 4 * i];
            d[0] = f2tf(v.x); d[1] = f2tf(v.y);
            d[2] = f2tf(v.z); d[3] = f2tf(v.w);
        }
        __syncthreads();

#pragma unroll
        for (int ks = 0; ks < KT / 8; ks++) {
            unsigned a[4][4];
#pragma unroll
            for (int mi = 0; mi < 4; mi++) {
                int r = (wm + mi * 16 + g) * AST + ks * 8 + tig;
                a[mi][0] = As[r];
                a[mi][1] = As[r + 8 * AST];
                a[mi][2] = As[r + 4];
                a[mi][3] = As[r + 8 * AST + 4];
            }
            unsigned bf[8][2];
#pragma unroll
            for (int ni = 0; ni < 8; ni++) {
                int r = (wn + ni * 8 + g) * AST + ks * 8 + tig;
                bf[ni][0] = Ws[r];
                bf[ni][1] = Ws[r + 4];
            }
#pragma unroll
            for (int mi = 0; mi < 4; mi++)
#pragma unroll
                for (int ni = 0; ni < 8; ni++)
                    mma_tf32v(acc[mi][ni], a[mi][0], a[mi][1], a[mi][2],
                              a[mi][3], bf[ni][0], bf[ni][1]);
        }
    }

#pragma unroll
    for (int mi = 0; mi < 4; mi++) {
#pragma unroll
        for (int ni = 0; ni < 8; ni++) {
            int row = bm + wm + mi * 16 + g;
            int col = bn + wn + ni * 8 + 2 * tig;
            *(float2*)&C[(size_t)row * N + col] =
                make_float2(acc[mi][ni][0], acc[mi][ni][1]);
            *(float2*)&C[(size_t)(row + 8) * N + col] =
                make_float2(acc[mi][ni][2], acc[mi][ni][3]);
        }
    }
}

// Fused Q/K/V projection: grid.x 0..7 -> Q cols, 8..9 -> K, 10..11 -> V
__global__ void __launch_bounds__(128) k_gemm_qkv(const float* __restrict__ x,
                                                  const float* __restrict__ Wq,
                                                  const float* __restrict__ Wk,
                                                  const float* __restrict__ Wv) {
    int bx = blockIdx.x;
    const float* W;
    float* C;
    int N, bn;
    if (bx < 8)       { W = Wq; C = g_qraw; N = D_;  bn = bx * 128; }
    else if (bx < 10) { W = Wk; C = g_kraw; N = KV_; bn = (bx - 8) * 128; }
    else              { W = Wv; C = g_vraw; N = KV_; bn = (bx - 10) * 128; }
    gemm_tf32(x, W, C, D_, N, blockIdx.y * 128, bn);
}

__global__ void __launch_bounds__(128) k_gemm_o(const float* __restrict__ W,
                                                float* __restrict__ out) {
    gemm_tf32(g_y, W, out, D_, D_, blockIdx.y * 128, blockIdx.x * 128);
}

// ---------------- RMSNorm + RoPE (+gain*scale for q), one warp per head ----
__global__ void __launch_bounds__(256) k_qprep(const float* __restrict__ gain) {
    int wid = (blockIdx.x * blockDim.x + threadIdx.x) >> 5;
    int lane = threadIdx.x & 31;
    int h = wid & (H_ - 1);
    int t = (wid >> 4) & (T_ - 1);
    int b = wid >> 15;
    const float* src = g_qraw + (size_t)(b * T_ + t) * D_ + h * HD_;
    float x1 = src[lane], x2 = src[lane + 32];
    float ss = x1 * x1 + x2 * x2;
#pragma unroll
    for (int o = 16; o > 0; o >>= 1) ss += __shfl_xor_sync(0xffffffffu, ss, o);
    float r = rsqrtf(ss * (1.0f / 64.0f) + EPS_);
    x1 *= r; x2 *= r;
    float f = (float)t * g_invf[lane];
    float s, c;
    sincosf(f, &s, &c);
    float g = gain[h] * 0.125f;  // fold attention scale hd^-0.5 into q
    float* dst = g_q + ((size_t)(b * H_ + h) * T_ + t) * HD_;
    dst[lane]      = (x1 * c + x2 * s) * g;
    dst[lane + 32] = (x2 * c - x1 * s) * g;
}

__global__ void __launch_bounds__(256) k_kprep() {
    int wid = (blockIdx.x * blockDim.x + threadIdx.x) >> 5;
    int lane = threadIdx.x & 31;
    int h = wid & (HKV_ - 1);
    int t = (wid >> 2) & (T_ - 1);
    int b = wid >> 13;
    const float* src = g_kraw + (size_t)(b * T_ + t) * KV_ + h * HD_;
    float x1 = src[lane], x2 = src[lane + 32];
    float ss = x1 * x1 + x2 * x2;
#pragma unroll
    for (int o = 16; o > 0; o >>= 1) ss += __shfl_xor_sync(0xffffffffu, ss, o);
    float r = rsqrtf(ss * (1.0f / 64.0f) + EPS_);
    x1 *= r; x2 *= r;
    float f = (float)t * g_invf[lane];
    float s, c;
    sincosf(f, &s, &c);
    float* dst = g_k + ((size_t)(b * HKV_ + h) * T_ + t) * HD_;
    dst[lane]      = x1 * c + x2 * s;
    dst[lane + 32] = x2 * c - x1 * s;
}

// ---------------- flash attention, tf32 mma, BQ=128 BN=64 ------------------
// 8 warps, warp w owns q-rows [w*16, w*16+16). Q a-frags resident.
// V is read directly from g_vraw ([BT, 256], head offset) — no transpose pass.
extern __shared__ unsigned shf[];

__global__ void __launch_bounds__(256, 2) k_flash2() {
    unsigned* Ksh = shf;                       // [64][FST]
    unsigned* Vsh = shf + 64 * FST;            // [64][VST]
    unsigned* Psh = shf + 64 * FST + 64 * VST; // [128][FST]

    const int tid  = threadIdx.x;
    const int lane = tid & 31;
    const int w    = tid >> 5;
    const int g    = lane >> 2;   // 0..7
    const int tig  = lane & 3;    // 0..3
    const int wm   = w * 16;
    const int qb   = (int)gridDim.x - 1 - (int)blockIdx.x;  // heavy first
    const int h = blockIdx.y, b = blockIdx.z;
    const int hkv = h >> 2;

    const float* Qg = g_q + ((size_t)(b * H_ + h) * T_ + qb * 128) * HD_;
    const float* Kg = g_k + (size_t)(b * HKV_ + hkv) * T_ * HD_;
    const float* Vg = g_vraw + (size_t)b * T_ * KV_ + hkv * HD_;

    // stage Q tile [128][64] into Psh (tf32), then load resident a-frags
    {
        int lr = tid >> 1;
        int lc = (tid & 1) * 32;
        const float* p = Qg + lr * 64 + lc;
#pragma unroll
        for (int i = 0; i < 8; i++) {
            float4 v = *(const float4*)(p + 4 * i);
            unsigned* d = &Psh[lr * FST + lc + 4 * i];
            d[0] = f2tf(v.x); d[1] = f2tf(v.y);
            d[2] = f2tf(v.z); d[3] = f2tf(v.w);
        }
    }
    __syncthreads();
    unsigned qa[8][4];
#pragma unroll
    for (int ks = 0; ks < 8; ks++) {
        qa[ks][0] = Psh[(wm + g) * FST + ks * 8 + tig];
        qa[ks][1] = Psh[(wm + g + 8) * FST + ks * 8 + tig];
        qa[ks][2] = Psh[(wm + g) * FST + ks * 8 + tig + 4];
        qa[ks][3] = Psh[(wm + g + 8) * FST + ks * 8 + tig + 4];
    }

    float m0 = -1e30f, m1 = -1e30f, l0 = 0.0f, l1 = 0.0f;
    float o[8][4];
#pragma unroll
    for (int nt = 0; nt < 8; nt++)
#pragma unroll
        for (int r = 0; r < 4; r++) o[nt][r] = 0.0f;

    const int lr  = tid >> 2;         // 0..63 kv loader row
    const int lc4 = (tid & 3) * 16;   // kv loader col
    const int nkb = 2 * qb + 2;

    for (int kb = 0; kb < nkb; kb++) {
        const float* kp = Kg + (size_t)(kb * 64 + lr) * 64 + lc4;
        const float* vp = Vg + (size_t)(kb * 64 + lr) * KV_ + lc4;
        float4 kv[4], vv[4];
#pragma unroll
        for (int i = 0; i < 4; i++) {
            kv[i] = *(const float4*)(kp + 4 * i);
            vv[i] = *(const float4*)(vp + 4 * i);
        }
        __syncthreads();  // prior iter's mma reads of Ksh/Vsh complete
#pragma unroll
        for (int i = 0; i < 4; i++) {
            unsigned* dk = &Ksh[lr * FST + lc4 + 4 * i];
            dk[0] = f2tf(kv[i].x); dk[1] = f2tf(kv[i].y);
            dk[2] = f2tf(kv[i].z); dk[3] = f2tf(kv[i].w);
            unsigned* dv = &Vsh[lr * VST + lc4 + 4 * i];
            dv[0] = f2tf(vv[i].x); dv[1] = f2tf(vv[i].y);
            dv[2] = f2tf(vv[i].z); dv[3] = f2tf(vv[i].w);
        }
        __syncthreads();

        // S = Q @ K^T : per warp 16x64
        float s[8][4];
#pragma unroll
        for (int nt = 0; nt < 8; nt++)
#pragma unroll
            for (int r = 0; r < 4; r++) s[nt][r] = 0.0f;
#pragma unroll
        for (int ks = 0; ks < 8; ks++) {
#pragma unroll
            for (int nt = 0; nt < 8; nt++) {
                int base = (nt * 8 + g) * FST + ks * 8 + tig;
                mma_tf32v(s[nt], qa[ks][0], qa[ks][1], qa[ks][2], qa[ks][3],
                          Ksh[base], Ksh[base + 4]);
            }
        }

        // causal mask (only the two diagonal-touching key blocks)
        if (kb >= 2 * qb) {
            int row0 = qb * 128 + wm + g;
            int row1 = row0 + 8;
#pragma unroll
            for (int nt = 0; nt < 8; nt++) {
                int col = kb * 64 + nt * 8 + 2 * tig;
                if (col > row0)     s[nt][0] = -1e30f;
                if (col + 1 > row0) s[nt][1] = -1e30f;
                if (col > row1)     s[nt][2] = -1e30f;
                if (col + 1 > row1) s[nt][3] = -1e30f;
            }
        }

        // online softmax: row g (s[.][0..1]) and row g+8 (s[.][2..3])
        float mx0 = -1e30f, mx1 = -1e30f;
#pragma unroll
        for (int nt = 0; nt < 8; nt++) {
            mx0 = fmaxf(mx0, fmaxf(s[nt][0], s[nt][1]));
            mx1 = fmaxf(mx1, fmaxf(s[nt][2], s[nt][3]));
        }
        mx0 = fmaxf(mx0, __shfl_xor_sync(0xffffffffu, mx0, 1));
        mx0 = fmaxf(mx0, __shfl_xor_sync(0xffffffffu, mx0, 2));
        mx1 = fmaxf(mx1, __shfl_xor_sync(0xffffffffu, mx1, 1));
        mx1 = fmaxf(mx1, __shfl_xor_sync(0xffffffffu, mx1, 2));
        float nm0 = fmaxf(m0, mx0), nm1 = fmaxf(m1, mx1);
        float c0 = __expf(m0 - nm0), c1 = __expf(m1 - nm1);
        float rs0 = 0.0f, rs1 = 0.0f;
#pragma unroll
        for (int nt = 0; nt < 8; nt++) {
            s[nt][0] = __expf(s[nt][0] - nm0);
            s[nt][1] = __expf(s[nt][1] - nm0);
            s[nt][2] = __expf(s[nt][2] - nm1);
            s[nt][3] = __expf(s[nt][3] - nm1);
            rs0 += s[nt][0] + s[nt][1];
            rs1 += s[nt][2] + s[nt][3];
        }
        rs0 += __shfl_xor_sync(0xffffffffu, rs0, 1);
        rs0 += __shfl_xor_sync(0xffffffffu, rs0, 2);
        rs1 += __shfl_xor_sync(0xffffffffu, rs1, 1);
        rs1 += __shfl_xor_sync(0xffffffffu, rs1, 2);
        l0 = l0 * c0 + rs0;
        l1 = l1 * c1 + rs1;
        m0 = nm0; m1 = nm1;
#pragma unroll
        for (int nt = 0; nt < 8; nt++) {
            o[nt][0] *= c0; o[nt][1] *= c0;
            o[nt][2] *= c1; o[nt][3] *= c1;
        }

        // store P fragments (tf32) to own warp's rows; warp-local sync only
#pragma unroll
        for (int nt = 0; nt < 8; nt++) {
            int col = nt * 8 + 2 * tig;
            *(uint2*)&Psh[(wm + g) * FST + col] =
                make_uint2(f2tf(s[nt][0]), f2tf(s[nt][1]));
            *(uint2*)&Psh[(wm + g + 8) * FST + col] =
                make_uint2(f2tf(s[nt][2]), f2tf(s[nt][3]));
        }
        __syncwarp();

        // O += P @ V
#pragma unroll
        for (int ks = 0; ks < 8; ks++) {
            unsigned a0 = Psh[(wm + g) * FST + ks * 8 + tig];
            unsigned a1 = Psh[(wm + g + 8) * FST + ks * 8 + tig];
            unsigned a2 = Psh[(wm + g) * FST + ks * 8 + tig + 4];
            unsigned a3 = Psh[(wm + g + 8) * FST + ks * 8 + tig + 4];
#pragma unroll
            for (int nt = 0; nt < 8; nt++) {
                int base = (ks * 8 + tig) * VST + nt * 8 + g;
                mma_tf32v(o[nt], a0, a1, a2, a3,
                          Vsh[base], Vsh[base + 4 * VST]);
            }
        }
    }

    float inv0 = 1.0f / l0, inv1 = 1.0f / l1;
    int r0 = qb * 128 + wm + g;
    int r1 = r0 + 8;
#pragma unroll
    for (int nt = 0; nt < 8; nt++) {
        int col = h * HD_ + nt * 8 + 2 * tig;
        *(float2*)&g_y[(size_t)(b * T_ + r0) * D_ + col] =
            make_float2(o[nt][0] * inv0, o[nt][1] * inv0);
        *(float2*)&g_y[(size_t)(b * T_ + r1) * D_ + col] =
            make_float2(o[nt][2] * inv1, o[nt][3] * inv1);
    }
}

// ---------------- launch ----------------------------------------------------
extern "C" void kernel_launch(void* const* d_in, const int* in_sizes, int n_in,
                              void* d_out, int out_size) {
    const float* x    = (const float*)d_in[0];
    const float* Wq   = (const float*)d_in[1];
    const float* Wk   = (const float*)d_in[2];
    const float* Wv   = (const float*)d_in[3];
    const float* Wp   = (const float*)d_in[4];
    const float* gain = (const float*)d_in[5];
    float* out = (float*)d_out;

    k_freq<<<1, 32>>>();
    k_gemm_qkv<<<dim3(12, BT_ / 128), 128>>>(x, Wq, Wk, Wv);
    k_qprep<<<(B_ * T_ * H_) / 8, 256>>>(gain);
    k_kprep<<<(B_ * T_ * HKV_) / 8, 256>>>();

    int flash_smem = (64 * FST + 64 * VST + 128 * FST) * (int)sizeof(unsigned);
    cudaFuncSetAttribute(k_flash2, cudaFuncAttributeMaxDynamicSharedMemorySize,
                         flash_smem);
    k_flash2<<<dim3(T_ / 128, H_, B_), 256, flash_smem>>>();

    k_gemm_o<<<dim3(D_ / 128, BT_ / 128), 128>>>(Wp, out);
}

// round 9
// speedup vs baseline: 1.1393x; 1.1393x over previous
#include <cuda_runtime.h>
#include <math.h>

#define B_   2
#define T_   2048
#define D_   1024
#define H_   16
#define HKV_ 4
#define HD_  64
#define KV_  256
#define BT_  (B_ * T_)
#define EPS_ 1.1920928955078125e-07f
#define KT   32   // gemm K-tile
#define AST  36   // gemm smem row stride (words)
#define FST  68   // flash K/P smem stride (words)
#define VST  72   // flash V smem stride (words)

// ---------------- scratch (static device globals; no runtime alloc) --------
__device__ float g_qraw[BT_ * D_];          // [BT, 1024] raw q projection
__device__ float g_kraw[BT_ * KV_];         // [BT, 256]
__device__ float g_vraw[BT_ * KV_];         // [BT, 256] (flash reads V here)
__device__ float g_q[B_ * H_ * T_ * HD_];   // [B,H,T,hd] normed+rope+gain+scale
__device__ float g_k[B_ * HKV_ * T_ * HD_]; // [B,Hkv,T,hd] normed+rope
__device__ float g_y[BT_ * D_];             // attention output [BT, 1024]
__device__ float g_invf[32];                // rope inv_freq table

// ---------------- inv_freq table (double pow once) -------------------------
__global__ void k_freq() {
    int i = threadIdx.x;
    if (i < 32) g_invf[i] = (float)pow(10000.0, -(double)i / 32.0);
}

// ---------------- tf32 helpers ---------------------------------------------
__device__ __forceinline__ unsigned f2tf(float f) {
    unsigned r;
    asm("cvt.rna.tf32.f32 %0, %1;" : "=r"(r) : "f"(f));
    return r;
}

__device__ __forceinline__ void mma_tf32v(float c[4], unsigned a0, unsigned a1,
                                          unsigned a2, unsigned a3,
                                          unsigned b0, unsigned b1) {
    asm volatile(
        "mma.sync.aligned.m16n8k8.row.col.f32.tf32.tf32.f32 "
        "{%0,%1,%2,%3}, {%4,%5,%6,%7}, {%8,%9}, {%0,%1,%2,%3};"
        : "+f"(c[0]), "+f"(c[1]), "+f"(c[2]), "+f"(c[3])
        : "r"(a0), "r"(a1), "r"(a2), "r"(a3), "r"(b0), "r"(b1));
}

// ---------------- tf32 GEMM: C[m,n] = sum_k A[m,k]*W[n,k] ------------------
// R4 layout: block 128x128xKT, 256 thr, 8 warps (2M x 4N), warp 64x32.
// STS-time tf32 conversion (identical numerics). Double-buffered smem,
// ONE __syncthreads per K-tile.
extern __shared__ unsigned shg2[];  // 2 x (As[128*AST] + Ws[128*AST])

__device__ __forceinline__ void gemm_tf32(const float* __restrict__ A,
                                          const float* __restrict__ W,
                                          float* __restrict__ C,
                                          int K, int N, int bm, int bn) {
    const int tid  = threadIdx.x;
    const int lane = tid & 31;
    const int w    = tid >> 5;
    const int g    = lane >> 2;     // 0..7
    const int tig  = lane & 3;      // 0..3
    const int wm   = (w & 1) * 64;  // warp M offset
    const int wn   = (w >> 1) * 32; // warp N offset

    const int lr  = tid >> 1;          // 0..127 loader row
    const int lcH = (tid & 1) * 16;    // loader col half
    const float* Ap = A + (size_t)(bm + lr) * K + lcH;
    const float* Wp = W + (size_t)(bn + lr) * K + lcH;

    float acc[4][4][4];
#pragma unroll
    for (int mi = 0; mi < 4; mi++)
#pragma unroll
        for (int ni = 0; ni < 4; ni++)
#pragma unroll
            for (int r = 0; r < 4; r++) acc[mi][ni][r] = 0.0f;

    const int nt = K / KT;
    float4 av[4], wv[4];
    // prologue: LDG tile 0 into registers
#pragma unroll
    for (int i = 0; i < 4; i++) {
        av[i] = *(const float4*)(Ap + 4 * i);
        wv[i] = *(const float4*)(Wp + 4 * i);
    }

    for (int t = 0; t < nt; t++) {
        unsigned* As = shg2 + (t & 1) * (2 * 128 * AST);
        unsigned* Ws = As + 128 * AST;

        // STS + cvt current tile (safe: previous reader of this buffer was
        // MMA(t-2), which precedes STS(t-1) -> sync(t-1) in all warps)
#pragma unroll
        for (int i = 0; i < 4; i++) {
            unsigned* pa = &As[lr * AST + lcH + 4 * i];
            pa[0] = f2tf(av[i].x); pa[1] = f2tf(av[i].y);
            pa[2] = f2tf(av[i].z); pa[3] = f2tf(av[i].w);
            unsigned* pw = &Ws[lr * AST + lcH + 4 * i];
            pw[0] = f2tf(wv[i].x); pw[1] = f2tf(wv[i].y);
            pw[2] = f2tf(wv[i].z); pw[3] = f2tf(wv[i].w);
        }
        __syncthreads();

        if (t + 1 < nt) {  // LDG next tile; latency overlaps MMA below
            const float* Apn = Ap + (t + 1) * KT;
            const float* Wpn = Wp + (t + 1) * KT;
#pragma unroll
            for (int i = 0; i < 4; i++) {
                av[i] = *(const float4*)(Apn + 4 * i);
                wv[i] = *(const float4*)(Wpn + 4 * i);
            }
        }

#pragma unroll
        for (int ks = 0; ks < KT / 8; ks++) {
            unsigned bfr[4][2];
#pragma unroll
            for (int ni = 0; ni < 4; ni++) {
                int r = (wn + ni * 8 + g) * AST + ks * 8 + tig;
                bfr[ni][0] = Ws[r];
                bfr[ni][1] = Ws[r + 4];
            }
#pragma unroll
            for (int mi = 0; mi < 4; mi++) {
                int r = (wm + mi * 16 + g) * AST + ks * 8 + tig;
                unsigned a0 = As[r];
                unsigned a2 = As[r + 4];
                unsigned a1 = As[r + 8 * AST];
                unsigned a3 = As[r + 8 * AST + 4];
#pragma unroll
                for (int ni = 0; ni < 4; ni++)
                    mma_tf32v(acc[mi][ni], a0, a1, a2, a3,
                              bfr[ni][0], bfr[ni][1]);
            }
        }
    }

#pragma unroll
    for (int mi = 0; mi < 4; mi++) {
#pragma unroll
        for (int ni = 0; ni < 4; ni++) {
            int row = bm + wm + mi * 16 + g;
            int col = bn + wn + ni * 8 + 2 * tig;
            *(float2*)&C[(size_t)row * N + col] =
                make_float2(acc[mi][ni][0], acc[mi][ni][1]);
            *(float2*)&C[(size_t)(row + 8) * N + col] =
                make_float2(acc[mi][ni][2], acc[mi][ni][3]);
        }
    }
}

// Fused Q/K/V projection: grid.x 0..7 -> Q cols, 8..9 -> K, 10..11 -> V
__global__ void __launch_bounds__(256) k_gemm_qkv(const float* __restrict__ x,
                                                  const float* __restrict__ Wq,
                                                  const float* __restrict__ Wk,
                                                  const float* __restrict__ Wv) {
    int bx = blockIdx.x;
    const float* W;
    float* C;
    int N, bn;
    if (bx < 8)       { W = Wq; C = g_qraw; N = D_;  bn = bx * 128; }
    else if (bx < 10) { W = Wk; C = g_kraw; N = KV_; bn = (bx - 8) * 128; }
    else              { W = Wv; C = g_vraw; N = KV_; bn = (bx - 10) * 128; }
    gemm_tf32(x, W, C, D_, N, blockIdx.y * 128, bn);
}

__global__ void __launch_bounds__(256) k_gemm_o(const float* __restrict__ W,
                                                float* __restrict__ out) {
    gemm_tf32(g_y, W, out, D_, D_, blockIdx.y * 128, blockIdx.x * 128);
}

// ---- merged RMSNorm + RoPE prep: q warps [0, 65536), k warps [65536, 81920)
__global__ void __launch_bounds__(256) k_prep(const float* __restrict__ gain) {
    int wid = (blockIdx.x * blockDim.x + threadIdx.x) >> 5;
    int lane = threadIdx.x & 31;
    if (wid < B_ * T_ * H_) {  // ---- q path
        int h = wid & (H_ - 1);
        int t = (wid >> 4) & (T_ - 1);
        int b = wid >> 15;
        const float* src = g_qraw + (size_t)(b * T_ + t) * D_ + h * HD_;
        float x1 = src[lane], x2 = src[lane + 32];
        float ss = x1 * x1 + x2 * x2;
#pragma unroll
        for (int o = 16; o > 0; o >>= 1) ss += __shfl_xor_sync(0xffffffffu, ss, o);
        float r = rsqrtf(ss * (1.0f / 64.0f) + EPS_);
        x1 *= r; x2 *= r;
        float f = (float)t * g_invf[lane];
        float s, c;
        sincosf(f, &s, &c);
        float g = gain[h] * 0.125f;  // fold attention scale hd^-0.5 into q
        float* dst = g_q + ((size_t)(b * H_ + h) * T_ + t) * HD_;
        dst[lane]      = (x1 * c + x2 * s) * g;
        dst[lane + 32] = (x2 * c - x1 * s) * g;
    } else {                   // ---- k path
        int kw = wid - B_ * T_ * H_;
        int h = kw & (HKV_ - 1);
        int t = (kw >> 2) & (T_ - 1);
        int b = kw >> 13;
        const float* src = g_kraw + (size_t)(b * T_ + t) * KV_ + h * HD_;
        float x1 = src[lane], x2 = src[lane + 32];
        float ss = x1 * x1 + x2 * x2;
#pragma unroll
        for (int o = 16; o > 0; o >>= 1) ss += __shfl_xor_sync(0xffffffffu, ss, o);
        float r = rsqrtf(ss * (1.0f / 64.0f) + EPS_);
        x1 *= r; x2 *= r;
        float f = (float)t * g_invf[lane];
        float s, c;
        sincosf(f, &s, &c);
        float* dst = g_k + ((size_t)(b * HKV_ + h) * T_ + t) * HD_;
        dst[lane]      = x1 * c + x2 * s;
        dst[lane + 32] = x2 * c - x1 * s;
    }
}

// ---------------- flash attention, tf32 mma, BQ=128 BN=64 ------------------
// 8 warps, warp w owns q-rows [w*16, w*16+16). Q a-frags resident.
// V read directly from g_vraw ([BT, 256], head offset) — no transpose pass.
extern __shared__ unsigned shf[];

__global__ void __launch_bounds__(256, 2) k_flash2() {
    unsigned* Ksh = shf;                       // [64][FST]
    unsigned* Vsh = shf + 64 * FST;            // [64][VST]
    unsigned* Psh = shf + 64 * FST + 64 * VST; // [128][FST]

    const int tid  = threadIdx.x;
    const int lane = tid & 31;
    const int w    = tid >> 5;
    const int g    = lane >> 2;   // 0..7
    const int tig  = lane & 3;    // 0..3
    const int wm   = w * 16;
    const int qb   = (int)gridDim.x - 1 - (int)blockIdx.x;  // heavy first
    const int h = blockIdx.y, b = blockIdx.z;
    const int hkv = h >> 2;

    const float* Qg = g_q + ((size_t)(b * H_ + h) * T_ + qb * 128) * HD_;
    const float* Kg = g_k + (size_t)(b * HKV_ + hkv) * T_ * HD_;
    const float* Vg = g_vraw + (size_t)b * T_ * KV_ + hkv * HD_;

    // stage Q tile [128][64] into Psh (tf32), then load resident a-frags
    {
        int lr = tid >> 1;
        int lc = (tid & 1) * 32;
        const float* p = Qg + lr * 64 + lc;
#pragma unroll
        for (int i = 0; i < 8; i++) {
            float4 v = *(const float4*)(p + 4 * i);
            unsigned* d = &Psh[lr * FST + lc + 4 * i];
            d[0] = f2tf(v.x); d[1] = f2tf(v.y);
            d[2] = f2tf(v.z); d[3] = f2tf(v.w);
        }
    }
    __syncthreads();
    unsigned qa[8][4];
#pragma unroll
    for (int ks = 0; ks < 8; ks++) {
        qa[ks][0] = Psh[(wm + g) * FST + ks * 8 + tig];
        qa[ks][1] = Psh[(wm + g + 8) * FST + ks * 8 + tig];
        qa[ks][2] = Psh[(wm + g) * FST + ks * 8 + tig + 4];
        qa[ks][3] = Psh[(wm + g + 8) * FST + ks * 8 + tig + 4];
    }

    float m0 = -1e30f, m1 = -1e30f, l0 = 0.0f, l1 = 0.0f;
    float o[8][4];
#pragma unroll
    for (int nt = 0; nt < 8; nt++)
#pragma unroll
        for (int r = 0; r < 4; r++) o[nt][r] = 0.0f;

    const int lr  = tid >> 2;         // 0..63 kv loader row
    const int lc4 = (tid & 3) * 16;   // kv loader col
    const int nkb = 2 * qb + 2;

    for (int kb = 0; kb < nkb; kb++) {
        const float* kp = Kg + (size_t)(kb * 64 + lr) * 64 + lc4;
        const float* vp = Vg + (size_t)(kb * 64 + lr) * KV_ + lc4;
        float4 kv[4], vv[4];
#pragma unroll
        for (int i = 0; i < 4; i++) {
            kv[i] = *(const float4*)(kp + 4 * i);
            vv[i] = *(const float4*)(vp + 4 * i);
        }
        __syncthreads();  // prior iter's mma reads of Ksh/Vsh complete
#pragma unroll
        for (int i = 0; i < 4; i++) {
            unsigned* dk = &Ksh[lr * FST + lc4 + 4 * i];
            dk[0] = f2tf(kv[i].x); dk[1] = f2tf(kv[i].y);
            dk[2] = f2tf(kv[i].z); dk[3] = f2tf(kv[i].w);
            unsigned* dv = &Vsh[lr * VST + lc4 + 4 * i];
            dv[0] = f2tf(vv[i].x); dv[1] = f2tf(vv[i].y);
            dv[2] = f2tf(vv[i].z); dv[3] = f2tf(vv[i].w);
        }
        __syncthreads();

        // S = Q @ K^T : per warp 16x64
        float s[8][4];
#pragma unroll
        for (int nt = 0; nt < 8; nt++)
#pragma unroll
            for (int r = 0; r < 4; r++) s[nt][r] = 0.0f;
#pragma unroll
        for (int ks = 0; ks < 8; ks++) {
#pragma unroll
            for (int nt = 0; nt < 8; nt++) {
                int base = (nt * 8 + g) * FST + ks * 8 + tig;
                mma_tf32v(s[nt], qa[ks][0], qa[ks][1], qa[ks][2], qa[ks][3],
                          Ksh[base], Ksh[base + 4]);
            }
        }

        // causal mask (only the two diagonal-touching key blocks)
        if (kb >= 2 * qb) {
            int row0 = qb * 128 + wm + g;
            int row1 = row0 + 8;
#pragma unroll
            for (int nt = 0; nt < 8; nt++) {
                int col = kb * 64 + nt * 8 + 2 * tig;
                if (col > row0)     s[nt][0] = -1e30f;
                if (col + 1 > row0) s[nt][1] = -1e30f;
                if (col > row1)     s[nt][2] = -1e30f;
                if (col + 1 > row1) s[nt][3] = -1e30f;
            }
        }

        // online softmax: row g (s[.][0..1]) and row g+8 (s[.][2..3])
        float mx0 = -1e30f, mx1 = -1e30f;
#pragma unroll
        for (int nt = 0; nt < 8; nt++) {
            mx0 = fmaxf(mx0, fmaxf(s[nt][0], s[nt][1]));
            mx1 = fmaxf(mx1, fmaxf(s[nt][2], s[nt][3]));
        }
        mx0 = fmaxf(mx0, __shfl_xor_sync(0xffffffffu, mx0, 1));
        mx0 = fmaxf(mx0, __shfl_xor_sync(0xffffffffu, mx0, 2));
        mx1 = fmaxf(mx1, __shfl_xor_sync(0xffffffffu, mx1, 1));
        mx1 = fmaxf(mx1, __shfl_xor_sync(0xffffffffu, mx1, 2));
        float nm0 = fmaxf(m0, mx0), nm1 = fmaxf(m1, mx1);
        float c0 = __expf(m0 - nm0), c1 = __expf(m1 - nm1);
        float rs0 = 0.0f, rs1 = 0.0f;
#pragma unroll
        for (int nt = 0; nt < 8; nt++) {
            s[nt][0] = __expf(s[nt][0] - nm0);
            s[nt][1] = __expf(s[nt][1] - nm0);
            s[nt][2] = __expf(s[nt][2] - nm1);
            s[nt][3] = __expf(s[nt][3] - nm1);
            rs0 += s[nt][0] + s[nt][1];
            rs1 += s[nt][2] + s[nt][3];
        }
        rs0 += __shfl_xor_sync(0xffffffffu, rs0, 1);
        rs0 += __shfl_xor_sync(0xffffffffu, rs0, 2);
        rs1 += __shfl_xor_sync(0xffffffffu, rs1, 1);
        rs1 += __shfl_xor_sync(0xffffffffu, rs1, 2);
        l0 = l0 * c0 + rs0;
        l1 = l1 * c1 + rs1;
        m0 = nm0; m1 = nm1;
#pragma unroll
        for (int nt = 0; nt < 8; nt++) {
            o[nt][0] *= c0; o[nt][1] *= c0;
            o[nt][2] *= c1; o[nt][3] *= c1;
        }

        // store P fragments (tf32) to own warp's rows; warp-local sync only
#pragma unroll
        for (int nt = 0; nt < 8; nt++) {
            int col = nt * 8 + 2 * tig;
            *(uint2*)&Psh[(wm + g) * FST + col] =
                make_uint2(f2tf(s[nt][0]), f2tf(s[nt][1]));
            *(uint2*)&Psh[(wm + g + 8) * FST + col] =
                make_uint2(f2tf(s[nt][2]), f2tf(s[nt][3]));
        }
        __syncwarp();

        // O += P @ V
#pragma unroll
        for (int ks = 0; ks < 8; ks++) {
            unsigned a0 = Psh[(wm + g) * FST + ks * 8 + tig];
            unsigned a1 = Psh[(wm + g + 8) * FST + ks * 8 + tig];
            unsigned a2 = Psh[(wm + g) * FST + ks * 8 + tig + 4];
            unsigned a3 = Psh[(wm + g + 8) * FST + ks * 8 + tig + 4];
#pragma unroll
            for (int nt = 0; nt < 8; nt++) {
                int base = (ks * 8 + tig) * VST + nt * 8 + g;
                mma_tf32v(o[nt], a0, a1, a2, a3,
                          Vsh[base], Vsh[base + 4 * VST]);
            }
        }
    }

    float inv0 = 1.0f / l0, inv1 = 1.0f / l1;
    int r0 = qb * 128 + wm + g;
    int r1 = r0 + 8;
#pragma unroll
    for (int nt = 0; nt < 8; nt++) {
        int col = h * HD_ + nt * 8 + 2 * tig;
        *(float2*)&g_y[(size_t)(b * T_ + r0) * D_ + col] =
            make_float2(o[nt][0] * inv0, o[nt][1] * inv0);
        *(float2*)&g_y[(size_t)(b * T_ + r1) * D_ + col] =
            make_float2(o[nt][2] * inv1, o[nt][3] * inv1);
    }
}

// ---------------- launch ----------------------------------------------------
extern "C" void kernel_launch(void* const* d_in, const int* in_sizes, int n_in,
                              void* d_out, int out_size) {
    const float* x    = (const float*)d_in[0];
    const float* Wq   = (const float*)d_in[1];
    const float* Wk   = (const float*)d_in[2];
    const float* Wv   = (const float*)d_in[3];
    const float* Wp   = (const float*)d_in[4];
    const float* gain = (const float*)d_in[5];
    float* out = (float*)d_out;

    int gemm_smem = 2 * 2 * 128 * AST * (int)sizeof(unsigned);  // 73728 B
    cudaFuncSetAttribute(k_gemm_qkv, cudaFuncAttributeMaxDynamicSharedMemorySize,
                         gemm_smem);
    cudaFuncSetAttribute(k_gemm_o, cudaFuncAttributeMaxDynamicSharedMemorySize,
                         gemm_smem);

    k_freq<<<1, 32>>>();
    k_gemm_qkv<<<dim3(12, BT_ / 128), 256, gemm_smem>>>(x, Wq, Wk, Wv);
    k_prep<<<(B_ * T_ * H_ + B_ * T_ * HKV_) / 8, 256>>>(gain);

    int flash_smem = (64 * FST + 64 * VST + 128 * FST) * (int)sizeof(unsigned);
    cudaFuncSetAttribute(k_flash2, cudaFuncAttributeMaxDynamicSharedMemorySize,
                         flash_smem);
    k_flash2<<<dim3(T_ / 128, H_, B_), 256, flash_smem>>>();

    k_gemm_o<<<dim3(D_ / 128, BT_ / 128), 256, gemm_smem>>>(Wp, out);
}